// round 6
// baseline (speedup 1.0000x reference)
#include <cuda_runtime.h>

// Shapes (fixed by the reference setup_inputs):
//   predicted_noise [32, 4, 512, 512] f32   (d_in[0])
//   target_noise    [32, 4, 512, 512] f32   (d_in[1])
//   text_tokens     [32, 64] int64          (d_in[2], UNUSED by the math)
//   text_positions  [32, 64, 2] f32         (d_in[3])
// Output: 1 x f32 scalar.
//
// result = mean over (b,c,h,w) of (1 + 3*mask[b,h,w]) * (p - t)^2
// (WEIGHT = 1.0 collapses base_loss out of the expression).
//
// One kernel. Block = (batch, 16-row chunk). Mask slice built in SMEM from
// the 64 tokens; per-thread mask words preloaded to registers; streaming
// loop is 8 batched LDG.128 (4 channels x {p,q}) + pure FFMA math.

#define NB 32
#define NC 4
#define NH 512
#define NW 512
#define NT 64
#define BOX 5

#define ROWS_PER_BLOCK 16
#define GRID (NB * (NH / ROWS_PER_BLOCK))          // 1024
#define THREADS 256
#define N_ELEMS (NB * NC * NH * NW)                // 33554432
#define F4_PER_IMG (NH * NW / 4)                   // 65536 = 2^16
#define TILE_F4 (ROWS_PER_BLOCK * NW / 4)          // 2048 float4 per channel tile
#define JITERS (TILE_F4 / THREADS)                 // 8

__device__ float    g_partials[GRID];
__device__ unsigned g_count = 0;   // wraps to 0 via atomicInc each replay

__global__ void __launch_bounds__(THREADS, 4)
fused_loss_kernel(const float4* __restrict__ p,
                  const float4* __restrict__ q,
                  const float*  __restrict__ pos,
                  float* __restrict__ out) {
    __shared__ unsigned smask[ROWS_PER_BLOCK * (NW / 32)];  // 256 words = 1 KB
    __shared__ float    ssum[THREADS / 32];
    __shared__ bool     s_last;

    const int tid   = threadIdx.x;
    const int batch = blockIdx.x >> 5;
    const int chunk = blockIdx.x & 31;
    const int h0    = chunk * ROWS_PER_BLOCK;

    // ---- build mask slice for rows [h0, h0+16) in SMEM ----
    smask[tid] = 0u;          // 256 words, one per thread
    __syncthreads();
    if (tid < NT) {
        float x = pos[(batch * NT + tid) * 2 + 0];
        float y = pos[(batch * NT + tid) * 2 + 1];
        if (x > 0.0f && y > 0.0f) {
            int xp = (int)floorf(x * (float)NW);
            int yp = (int)floorf(y * (float)NH);
            int x0 = max(xp - BOX, 0);
            int x1 = min(xp + BOX, NW);
            int y0 = max(max(yp - BOX, 0), h0);
            int y1 = min(min(yp + BOX, NH), h0 + ROWS_PER_BLOCK);
            if (x0 < x1 && y0 < y1) {
                int w0 = x0 >> 5;
                int w1 = (x1 - 1) >> 5;
                unsigned m0, m1 = 0u;
                if (w0 == w1) {
                    m0 = ((1u << (x1 - x0)) - 1u) << (x0 & 31);   // width <= 10 < 32
                } else {
                    m0 = ~0u << (x0 & 31);
                    m1 = (1u << (x1 - (w1 << 5))) - 1u;           // 1..9 bits
                }
                for (int i = y0; i < y1; i++) {
                    int row = (i - h0) << 4;                      // *16 words/row
                    atomicOr(&smask[row + w0], m0);
                    if (w0 != w1) atomicOr(&smask[row + w1], m1);
                }
            }
        }
    }
    __syncthreads();

    // ---- preload this thread's 8 mask words; shift is loop-invariant ----
    // flat float4 index within tile: idx = tid + j*256; word = idx>>3,
    // bit group = (idx&7)*4, and idx&7 == tid&7 since 256 % 8 == 0.
    const int shift = (tid & 7) << 2;
    unsigned words[JITERS];
    #pragma unroll
    for (int j = 0; j < JITERS; j++)
        words[j] = smask[(tid + j * THREADS) >> 3];

    // ---- stream: per j, 8 independent LDG.128 (4 channels x {p,q}) ----
    const int base = ((batch * NC) << 16) + (h0 << 7);  // float4 index
    float s0 = 0.0f, s1 = 0.0f, s2 = 0.0f, s3 = 0.0f;

    #pragma unroll 2
    for (int j = 0; j < JITERS; j++) {
        const int idx = base + tid + j * THREADS;
        unsigned bits = words[j] >> shift;
        float w0 = 1.0f + 3.0f * (float)(bits & 1u);
        float w1 = 1.0f + 3.0f * (float)((bits >> 1) & 1u);
        float w2 = 1.0f + 3.0f * (float)((bits >> 2) & 1u);
        float w3 = 1.0f + 3.0f * (float)((bits >> 3) & 1u);

        float4 A[NC], B[NC];
        #pragma unroll
        for (int ch = 0; ch < NC; ch++) {
            A[ch] = __ldcs(&p[idx + (ch << 16)]);
            B[ch] = __ldcs(&q[idx + (ch << 16)]);
        }
        #pragma unroll
        for (int ch = 0; ch < NC; ch++) {
            float d0 = A[ch].x - B[ch].x;
            float d1 = A[ch].y - B[ch].y;
            float d2 = A[ch].z - B[ch].z;
            float d3 = A[ch].w - B[ch].w;
            s0 = fmaf(w0, d0 * d0, s0);
            s1 = fmaf(w1, d1 * d1, s1);
            s2 = fmaf(w2, d2 * d2, s2);
            s3 = fmaf(w3, d3 * d3, s3);
        }
    }
    float sum = (s0 + s1) + (s2 + s3);

    // ---- block reduce ----
    #pragma unroll
    for (int o = 16; o > 0; o >>= 1)
        sum += __shfl_xor_sync(0xFFFFFFFFu, sum, o);
    int lane = tid & 31, wid = tid >> 5;
    if (lane == 0) ssum[wid] = sum;
    __syncthreads();
    if (wid == 0) {
        float v = (lane < THREADS / 32) ? ssum[lane] : 0.0f;
        #pragma unroll
        for (int o = 4; o > 0; o >>= 1)
            v += __shfl_xor_sync(0xFFFFFFFFu, v, o);
        if (lane == 0) {
            g_partials[blockIdx.x] = v;
            __threadfence();
            unsigned prev = atomicInc(&g_count, GRID - 1);  // wraps to 0 after last
            s_last = (prev == GRID - 1);
        }
    }
    __syncthreads();

    // ---- last block folds partials, writes scalar ----
    if (s_last) {
        double d = 0.0;
        for (int i = tid; i < GRID; i += THREADS)
            d += (double)g_partials[i];
        #pragma unroll
        for (int o = 16; o > 0; o >>= 1)
            d += __shfl_xor_sync(0xFFFFFFFFu, d, o);
        __shared__ double dsum[THREADS / 32];
        if (lane == 0) dsum[wid] = d;
        __syncthreads();
        if (wid == 0) {
            double t = (lane < THREADS / 32) ? dsum[lane] : 0.0;
            #pragma unroll
            for (int o = 4; o > 0; o >>= 1)
                t += __shfl_xor_sync(0xFFFFFFFFu, t, o);
            if (lane == 0)
                out[0] = (float)(t * (1.0 / (double)N_ELEMS));
        }
    }
}

extern "C" void kernel_launch(void* const* d_in, const int* in_sizes, int n_in,
                              void* d_out, int out_size) {
    const float* pred = (const float*)d_in[0];
    const float* targ = (const float*)d_in[1];
    // d_in[2] (text_tokens) is unused by the math.
    const float* pos  = (const float*)d_in[3];
    fused_loss_kernel<<<GRID, THREADS>>>((const float4*)pred,
                                         (const float4*)targ,
                                         pos, (float*)d_out);
}